// round 1
// baseline (speedup 1.0000x reference)
#include <cuda_runtime.h>
#include <cuda_bf16.h>
#include <cstdint>

// Problem constants (fixed by the reference)
#define NN      50000
#define EE      800000
#define INDIM   512
#define HID     128
#define OUTD    128

// Scratch (allocation-free rule: __device__ globals). ~51.3 MB total.
__device__ float g_bufA[(size_t)NN * 128];
__device__ float g_bufB[(size_t)NN * 128];
__device__ float g_inv_out[NN];
__device__ float g_inv_in[NN];
__device__ int   g_deg_out[NN];
__device__ int   g_deg_in[NN];

// ---------------------------------------------------------------------------
// Degrees
// ---------------------------------------------------------------------------
__global__ void zero_deg_kernel() {
    int i = blockIdx.x * blockDim.x + threadIdx.x;
    if (i < NN) { g_deg_out[i] = 0; g_deg_in[i] = 0; }
}

__global__ void count_deg_kernel(const int* __restrict__ src,
                                 const int* __restrict__ dst) {
    int e = blockIdx.x * blockDim.x + threadIdx.x;
    if (e < EE) {
        atomicAdd(&g_deg_out[src[e]], 1);
        atomicAdd(&g_deg_in[dst[e]], 1);
    }
}

__global__ void inv_sqrt_kernel() {
    int i = blockIdx.x * blockDim.x + threadIdx.x;
    if (i < NN) {
        g_inv_out[i] = rsqrtf(fmaxf((float)g_deg_out[i], 1.0f));
        g_inv_in[i]  = rsqrtf(fmaxf((float)g_deg_in[i], 1.0f));
    }
}

// ---------------------------------------------------------------------------
// SGEMM: C[M,128] = (A[M,K] @ B[K,128]) * rowscale[row]
// BM=128, BN=128, BK=8, 256 threads, 8x8 per thread.
// ---------------------------------------------------------------------------
__global__ void __launch_bounds__(256)
sgemm_scaled_kernel(const float* __restrict__ A,
                    const float* __restrict__ B,
                    const float* __restrict__ rowscale,
                    float* __restrict__ C,
                    int M, int K)
{
    __shared__ float As[8][128];
    __shared__ float Bs[8][128];

    const int tid = threadIdx.x;
    const int block_row = blockIdx.x * 128;

    // A tile load mapping: one float4 per thread (128 rows x 8 k = 256 float4)
    const int arow = tid >> 1;
    const int ak4  = (tid & 1) * 4;
    // B tile load mapping: one float4 per thread (8 k x 128 cols = 256 float4)
    const int bk    = tid >> 5;
    const int bcol4 = (tid & 31) * 4;

    const int ty = tid >> 4;     // 0..15
    const int tx = tid & 15;     // 0..15
    const int row0 = ty * 8;
    const int col0 = tx * 8;

    float acc[8][8];
    #pragma unroll
    for (int i = 0; i < 8; i++)
        #pragma unroll
        for (int j = 0; j < 8; j++) acc[i][j] = 0.0f;

    for (int k0 = 0; k0 < K; k0 += 8) {
        // Load A tile (row-guarded), store transposed [k][m]
        float4 av = make_float4(0.f, 0.f, 0.f, 0.f);
        const int gr = block_row + arow;
        if (gr < M)
            av = *(const float4*)&A[(size_t)gr * K + k0 + ak4];
        As[ak4 + 0][arow] = av.x;
        As[ak4 + 1][arow] = av.y;
        As[ak4 + 2][arow] = av.z;
        As[ak4 + 3][arow] = av.w;

        // Load B tile (N=128 exact, K multiple of 8: no guard)
        *(float4*)&Bs[bk][bcol4] =
            *(const float4*)&B[(size_t)(k0 + bk) * 128 + bcol4];

        __syncthreads();

        #pragma unroll
        for (int kk = 0; kk < 8; kk++) {
            float ra[8], rb[8];
            *(float4*)&ra[0] = *(float4*)&As[kk][row0];
            *(float4*)&ra[4] = *(float4*)&As[kk][row0 + 4];
            *(float4*)&rb[0] = *(float4*)&Bs[kk][col0];
            *(float4*)&rb[4] = *(float4*)&Bs[kk][col0 + 4];
            #pragma unroll
            for (int i = 0; i < 8; i++)
                #pragma unroll
                for (int j = 0; j < 8; j++)
                    acc[i][j] = fmaf(ra[i], rb[j], acc[i][j]);
        }
        __syncthreads();
    }

    #pragma unroll
    for (int i = 0; i < 8; i++) {
        const int gr = block_row + row0 + i;
        if (gr < M) {
            const float s = rowscale[gr];
            float4 v0, v1;
            v0.x = acc[i][0] * s; v0.y = acc[i][1] * s;
            v0.z = acc[i][2] * s; v0.w = acc[i][3] * s;
            v1.x = acc[i][4] * s; v1.y = acc[i][5] * s;
            v1.z = acc[i][6] * s; v1.w = acc[i][7] * s;
            *(float4*)&C[(size_t)gr * 128 + col0]     = v0;
            *(float4*)&C[(size_t)gr * 128 + col0 + 4] = v1;
        }
    }
}

// ---------------------------------------------------------------------------
// Zero a [NN*128] float buffer (float4 stores)
// ---------------------------------------------------------------------------
__global__ void zero_buf_kernel(float* __restrict__ buf) {
    int i4 = blockIdx.x * blockDim.x + threadIdx.x;
    if (i4 < NN * 32)
        *(float4*)&buf[(size_t)i4 * 4] = make_float4(0.f, 0.f, 0.f, 0.f);
}

// ---------------------------------------------------------------------------
// Scatter-aggregate: agg[dst[e], :] += h[src[e], :]   (128 floats per edge)
// Warp per edge: 32 lanes x float4, vector reduction red.global.add.v4.f32
// ---------------------------------------------------------------------------
__global__ void __launch_bounds__(256)
scatter_kernel(const float* __restrict__ h,
               const int* __restrict__ src,
               const int* __restrict__ dst,
               float* __restrict__ agg)
{
    const int gid  = blockIdx.x * blockDim.x + threadIdx.x;
    const int e    = gid >> 5;
    const int lane = gid & 31;
    if (e < EE) {
        const int s = src[e];
        const int d = dst[e];
        const float4 v = *(const float4*)&h[(size_t)s * 128 + lane * 4];
        float* p = &agg[(size_t)d * 128 + lane * 4];
        asm volatile("red.global.add.v4.f32 [%0], {%1, %2, %3, %4};"
                     :: "l"(p), "f"(v.x), "f"(v.y), "f"(v.z), "f"(v.w)
                     : "memory");
    }
}

// ---------------------------------------------------------------------------
// Mid epilogue: out = relu(in * inv_in[row] + b1[col])    (float4 granularity)
// ---------------------------------------------------------------------------
__global__ void relu_mid_kernel(const float* __restrict__ in,
                                const float* __restrict__ b1,
                                float* __restrict__ out)
{
    int i4 = blockIdx.x * blockDim.x + threadIdx.x;
    if (i4 < NN * 32) {
        const int row  = i4 >> 5;
        const int col4 = (i4 & 31) * 4;
        const float s = g_inv_in[row];
        const float4 v = *(const float4*)&in[(size_t)i4 * 4];
        const float4 b = *(const float4*)&b1[col4];
        float4 r;
        r.x = fmaxf(fmaf(v.x, s, b.x), 0.f);
        r.y = fmaxf(fmaf(v.y, s, b.y), 0.f);
        r.z = fmaxf(fmaf(v.z, s, b.z), 0.f);
        r.w = fmaxf(fmaf(v.w, s, b.w), 0.f);
        *(float4*)&out[(size_t)i4 * 4] = r;
    }
}

// ---------------------------------------------------------------------------
// Final epilogue: out = in * inv_in[row] + b2[col]
// ---------------------------------------------------------------------------
__global__ void final_kernel(const float* __restrict__ in,
                             const float* __restrict__ b2,
                             float* __restrict__ out)
{
    int i4 = blockIdx.x * blockDim.x + threadIdx.x;
    if (i4 < NN * 32) {
        const int row  = i4 >> 5;
        const int col4 = (i4 & 31) * 4;
        const float s = g_inv_in[row];
        const float4 v = *(const float4*)&in[(size_t)i4 * 4];
        const float4 b = *(const float4*)&b2[col4];
        float4 r;
        r.x = fmaf(v.x, s, b.x);
        r.y = fmaf(v.y, s, b.y);
        r.z = fmaf(v.z, s, b.z);
        r.w = fmaf(v.w, s, b.w);
        *(float4*)&out[(size_t)i4 * 4] = r;
    }
}

// ---------------------------------------------------------------------------
// Host-side: one full encoder
// ---------------------------------------------------------------------------
static void run_encoder(const float* feat, const int* src, const int* dst,
                        const float* W1, const float* b1,
                        const float* W2, const float* b2,
                        float* out)
{
    float* bufA;
    float* bufB;
    cudaGetSymbolAddress((void**)&bufA, g_bufA);
    cudaGetSymbolAddress((void**)&bufB, g_bufB);
    float* inv_out;
    cudaGetSymbolAddress((void**)&inv_out, g_inv_out);

    const int nThreads = 256;
    const int gridN    = (NN + nThreads - 1) / nThreads;          // 196
    const int gridE    = (EE + nThreads - 1) / nThreads;          // 3125
    const int gridBuf  = (NN * 32 + nThreads - 1) / nThreads;     // 6250
    const int gridScat = (EE * 32 + nThreads - 1) / nThreads;     // 100000
    const int gridGemm = (NN + 127) / 128;                         // 391

    // Degrees + normalization factors
    zero_deg_kernel<<<gridN, nThreads>>>();
    count_deg_kernel<<<gridE, nThreads>>>(src, dst);
    inv_sqrt_kernel<<<gridN, nThreads>>>();

    // Layer 1: bufA = (feat @ W1) * inv_out
    sgemm_scaled_kernel<<<gridGemm, nThreads>>>(feat, W1, inv_out, bufA, NN, INDIM);
    // bufB = scatter(bufA)
    zero_buf_kernel<<<gridBuf, nThreads>>>(bufB);
    scatter_kernel<<<gridScat, nThreads>>>(bufA, src, dst, bufB);
    // bufA = relu(bufB * inv_in + b1)
    relu_mid_kernel<<<gridBuf, nThreads>>>(bufB, b1, bufA);

    // Layer 2: bufB = (bufA @ W2) * inv_out
    sgemm_scaled_kernel<<<gridGemm, nThreads>>>(bufA, W2, inv_out, bufB, NN, HID);
    // bufA = scatter(bufB)
    zero_buf_kernel<<<gridBuf, nThreads>>>(bufA);
    scatter_kernel<<<gridScat, nThreads>>>(bufB, src, dst, bufA);
    // out = bufA * inv_in + b2
    final_kernel<<<gridBuf, nThreads>>>(bufA, b2, out);
}

extern "C" void kernel_launch(void* const* d_in, const int* in_sizes, int n_in,
                              void* d_out, int out_size)
{
    // metadata order: feat1, src1, dst1, feat2, src2, dst2, feat, src, dst,
    //                 W1, b1, W2, b2
    const float* feat1 = (const float*)d_in[0];
    const int*   src1  = (const int*)  d_in[1];
    const int*   dst1  = (const int*)  d_in[2];
    const float* feat2 = (const float*)d_in[3];
    const int*   src2  = (const int*)  d_in[4];
    const int*   dst2  = (const int*)  d_in[5];
    const float* feat  = (const float*)d_in[6];
    const int*   src   = (const int*)  d_in[7];
    const int*   dst   = (const int*)  d_in[8];
    const float* W1    = (const float*)d_in[9];
    const float* b1    = (const float*)d_in[10];
    const float* W2    = (const float*)d_in[11];
    const float* b2    = (const float*)d_in[12];

    float* out = (float*)d_out;
    const size_t enc_elems = (size_t)NN * OUTD;

    run_encoder(feat1, src1, dst1, W1, b1, W2, b2, out);
    run_encoder(feat2, src2, dst2, W1, b1, W2, b2, out + enc_elems);
    run_encoder(feat,  src,  dst,  W1, b1, W2, b2, out + 2 * enc_elems);
}

// round 2
// speedup vs baseline: 1.0430x; 1.0430x over previous
#include <cuda_runtime.h>
#include <cuda_bf16.h>
#include <cstdint>

#define NN      50000
#define EE      800000
#define INDIM   512
#define HID     128
#define OUTD    128

// Scratch (__device__ globals; allocation-free rule). ~55 MB.
__device__ float g_bufA[(size_t)NN * 128];
__device__ float g_bufB[(size_t)NN * 128];
__device__ float g_inv_out[NN];
__device__ float g_inv_in[NN];
__device__ int   g_deg_out[NN];
__device__ int   g_deg_in[NN];
__device__ int   g_offsets[NN + 1];
__device__ int   g_cursor[NN];
__device__ int   g_eidx[EE];          // src node id per in-edge, grouped by dst

// ---------------------------------------------------------------------------
// Degrees
// ---------------------------------------------------------------------------
__global__ void zero_deg_kernel() {
    int i = blockIdx.x * blockDim.x + threadIdx.x;
    if (i < NN) { g_deg_out[i] = 0; g_deg_in[i] = 0; }
}

__global__ void count_deg_kernel(const int* __restrict__ src,
                                 const int* __restrict__ dst) {
    int e = blockIdx.x * blockDim.x + threadIdx.x;
    if (e < EE) {
        atomicAdd(&g_deg_out[src[e]], 1);
        atomicAdd(&g_deg_in[dst[e]], 1);
    }
}

__global__ void inv_sqrt_kernel() {
    int i = blockIdx.x * blockDim.x + threadIdx.x;
    if (i < NN) {
        g_inv_out[i] = rsqrtf(fmaxf((float)g_deg_out[i], 1.0f));
        g_inv_in[i]  = rsqrtf(fmaxf((float)g_deg_in[i], 1.0f));
    }
}

// ---------------------------------------------------------------------------
// Exclusive scan of deg_in -> offsets (+ copy into cursor). One block.
// ---------------------------------------------------------------------------
__global__ void __launch_bounds__(1024)
scan_kernel() {
    __shared__ int partial[1024];
    const int T = 1024;
    const int tid = threadIdx.x;
    const int chunk = (NN + T - 1) / T;         // 49
    const int start = tid * chunk;
    const int end   = min(start + chunk, NN);

    int sum = 0;
    for (int i = start; i < end; i++) sum += g_deg_in[i];
    partial[tid] = sum;
    __syncthreads();

    // Hillis-Steele inclusive scan over 1024 partials
    for (int off = 1; off < T; off <<= 1) {
        int t = 0;
        if (tid >= off) t = partial[tid - off];
        __syncthreads();
        partial[tid] += t;
        __syncthreads();
    }

    int run = partial[tid] - sum;               // exclusive base
    for (int i = start; i < end; i++) {
        g_offsets[i] = run;
        g_cursor[i]  = run;
        run += g_deg_in[i];
    }
    if (tid == T - 1) g_offsets[NN] = run;
}

// ---------------------------------------------------------------------------
// Fill CSR: group src ids by dst
// ---------------------------------------------------------------------------
__global__ void fill_csr_kernel(const int* __restrict__ src,
                                const int* __restrict__ dst) {
    int e = blockIdx.x * blockDim.x + threadIdx.x;
    if (e < EE) {
        int pos = atomicAdd(&g_cursor[dst[e]], 1);
        g_eidx[pos] = src[e];
    }
}

// ---------------------------------------------------------------------------
// SGEMM: C[M,128] = (A[M,K] @ B[K,128]) * rowscale[row]
// BM=128, BN=128, BK=8, 256 threads, 8x8/thread, double-buffered smem.
// ---------------------------------------------------------------------------
__global__ void __launch_bounds__(256)
sgemm_scaled_kernel(const float* __restrict__ A,
                    const float* __restrict__ B,
                    const float* __restrict__ rowscale,
                    float* __restrict__ C,
                    int M, int K)
{
    __shared__ float As[2][8][128];
    __shared__ float Bs[2][8][128];

    const int tid = threadIdx.x;
    const int block_row = blockIdx.x * 128;

    const int arow = tid >> 1;
    const int ak4  = (tid & 1) * 4;
    const int bk    = tid >> 5;
    const int bcol4 = (tid & 31) * 4;

    const int ty = tid >> 4;
    const int tx = tid & 15;
    const int row0 = ty * 8;
    const int col0 = tx * 8;

    float acc[8][8];
    #pragma unroll
    for (int i = 0; i < 8; i++)
        #pragma unroll
        for (int j = 0; j < 8; j++) acc[i][j] = 0.0f;

    const int gr = block_row + arow;
    const bool a_ok = (gr < M);

    // Prologue: load first tile
    float4 av = make_float4(0.f, 0.f, 0.f, 0.f);
    if (a_ok) av = *(const float4*)&A[(size_t)gr * K + ak4];
    float4 bv = *(const float4*)&B[(size_t)bk * 128 + bcol4];

    As[0][ak4 + 0][arow] = av.x;
    As[0][ak4 + 1][arow] = av.y;
    As[0][ak4 + 2][arow] = av.z;
    As[0][ak4 + 3][arow] = av.w;
    *(float4*)&Bs[0][bk][bcol4] = bv;
    __syncthreads();

    int cur = 0;
    for (int k0 = 0; k0 < K; k0 += 8) {
        const bool has_next = (k0 + 8 < K);
        if (has_next) {
            av = make_float4(0.f, 0.f, 0.f, 0.f);
            if (a_ok) av = *(const float4*)&A[(size_t)gr * K + k0 + 8 + ak4];
            bv = *(const float4*)&B[(size_t)(k0 + 8 + bk) * 128 + bcol4];
        }

        #pragma unroll
        for (int kk = 0; kk < 8; kk++) {
            float ra[8], rb[8];
            *(float4*)&ra[0] = *(float4*)&As[cur][kk][row0];
            *(float4*)&ra[4] = *(float4*)&As[cur][kk][row0 + 4];
            *(float4*)&rb[0] = *(float4*)&Bs[cur][kk][col0];
            *(float4*)&rb[4] = *(float4*)&Bs[cur][kk][col0 + 4];
            #pragma unroll
            for (int i = 0; i < 8; i++)
                #pragma unroll
                for (int j = 0; j < 8; j++)
                    acc[i][j] = fmaf(ra[i], rb[j], acc[i][j]);
        }

        if (has_next) {
            const int nxt = cur ^ 1;
            As[nxt][ak4 + 0][arow] = av.x;
            As[nxt][ak4 + 1][arow] = av.y;
            As[nxt][ak4 + 2][arow] = av.z;
            As[nxt][ak4 + 3][arow] = av.w;
            *(float4*)&Bs[nxt][bk][bcol4] = bv;
            __syncthreads();
            cur = nxt;
        }
    }

    #pragma unroll
    for (int i = 0; i < 8; i++) {
        const int grr = block_row + row0 + i;
        if (grr < M) {
            const float s = rowscale[grr];
            float4 v0, v1;
            v0.x = acc[i][0] * s; v0.y = acc[i][1] * s;
            v0.z = acc[i][2] * s; v0.w = acc[i][3] * s;
            v1.x = acc[i][4] * s; v1.y = acc[i][5] * s;
            v1.z = acc[i][6] * s; v1.w = acc[i][7] * s;
            *(float4*)&C[(size_t)grr * 128 + col0]     = v0;
            *(float4*)&C[(size_t)grr * 128 + col0 + 4] = v1;
        }
    }
}

// ---------------------------------------------------------------------------
// CSR aggregation + fused epilogue:
//   out[d,:] = act( (sum_{e: dst=d} h[src_e,:]) * inv_in[d] + bias[:] )
// One warp per dst node; lane handles 4 floats.
// ---------------------------------------------------------------------------
template <bool DO_RELU>
__global__ void __launch_bounds__(256)
aggregate_kernel(const float* __restrict__ h,
                 const float* __restrict__ bias,
                 float* __restrict__ out)
{
    const int gid  = blockIdx.x * blockDim.x + threadIdx.x;
    const int d    = gid >> 5;
    const int lane = threadIdx.x & 31;
    if (d >= NN) return;

    const int beg = g_offsets[d];
    const int end = g_offsets[d + 1];

    float4 acc = make_float4(0.f, 0.f, 0.f, 0.f);
    for (int j = beg; j < end; j++) {
        const int s = g_eidx[j];
        const float4 v = *(const float4*)&h[(size_t)s * 128 + lane * 4];
        acc.x += v.x; acc.y += v.y; acc.z += v.z; acc.w += v.w;
    }

    const float sc = g_inv_in[d];
    const float4 b = *(const float4*)&bias[lane * 4];
    float4 r;
    r.x = fmaf(acc.x, sc, b.x);
    r.y = fmaf(acc.y, sc, b.y);
    r.z = fmaf(acc.z, sc, b.z);
    r.w = fmaf(acc.w, sc, b.w);
    if (DO_RELU) {
        r.x = fmaxf(r.x, 0.f); r.y = fmaxf(r.y, 0.f);
        r.z = fmaxf(r.z, 0.f); r.w = fmaxf(r.w, 0.f);
    }
    *(float4*)&out[(size_t)d * 128 + lane * 4] = r;
}

// ---------------------------------------------------------------------------
// Host-side: one full encoder
// ---------------------------------------------------------------------------
static void run_encoder(const float* feat, const int* src, const int* dst,
                        const float* W1, const float* b1,
                        const float* W2, const float* b2,
                        float* out)
{
    float* bufA;
    float* bufB;
    float* inv_out;
    cudaGetSymbolAddress((void**)&bufA, g_bufA);
    cudaGetSymbolAddress((void**)&bufB, g_bufB);
    cudaGetSymbolAddress((void**)&inv_out, g_inv_out);

    const int nT = 256;
    const int gridN    = (NN + nT - 1) / nT;
    const int gridE    = (EE + nT - 1) / nT;
    const int gridGemm = (NN + 127) / 128;
    const int gridAgg  = (NN * 32 + nT - 1) / nT;   // warp per node

    // Graph structure (built once, reused by both layers)
    zero_deg_kernel<<<gridN, nT>>>();
    count_deg_kernel<<<gridE, nT>>>(src, dst);
    inv_sqrt_kernel<<<gridN, nT>>>();
    scan_kernel<<<1, 1024>>>();
    fill_csr_kernel<<<gridE, nT>>>(src, dst);

    // Layer 1
    sgemm_scaled_kernel<<<gridGemm, nT>>>(feat, W1, inv_out, bufA, NN, INDIM);
    aggregate_kernel<true><<<gridAgg, nT>>>(bufA, b1, bufB);

    // Layer 2
    sgemm_scaled_kernel<<<gridGemm, nT>>>(bufB, W2, inv_out, bufA, NN, HID);
    aggregate_kernel<false><<<gridAgg, nT>>>(bufA, b2, out);
}

extern "C" void kernel_launch(void* const* d_in, const int* in_sizes, int n_in,
                              void* d_out, int out_size)
{
    const float* feat1 = (const float*)d_in[0];
    const int*   src1  = (const int*)  d_in[1];
    const int*   dst1  = (const int*)  d_in[2];
    const float* feat2 = (const float*)d_in[3];
    const int*   src2  = (const int*)  d_in[4];
    const int*   dst2  = (const int*)  d_in[5];
    const float* feat  = (const float*)d_in[6];
    const int*   src   = (const int*)  d_in[7];
    const int*   dst   = (const int*)  d_in[8];
    const float* W1    = (const float*)d_in[9];
    const float* b1    = (const float*)d_in[10];
    const float* W2    = (const float*)d_in[11];
    const float* b2    = (const float*)d_in[12];

    float* out = (float*)d_out;
    const size_t enc_elems = (size_t)NN * OUTD;

    run_encoder(feat1, src1, dst1, W1, b1, W2, b2, out);
    run_encoder(feat2, src2, dst2, W1, b1, W2, b2, out + enc_elems);
    run_encoder(feat,  src,  dst,  W1, b1, W2, b2, out + 2 * enc_elems);
}

// round 3
// speedup vs baseline: 1.6158x; 1.5492x over previous
#include <cuda_runtime.h>
#include <cuda_bf16.h>
#include <cstdint>

#define NN      50000
#define EE      800000
#define INDIM   512
#define HID     128
#define OUTD    128
#define NB      196                       // scan blocks per graph (ceil(NN/256))

struct Ptrs3 {
    const int*   src[3];
    const int*   dst[3];
    const float* feat[3];
};

// Scratch (__device__ globals). ~167 MB.
__device__ float g_h[3][(size_t)NN * 128];     // GEMM outputs
__device__ float g_a[3][(size_t)NN * 128];     // aggregation outputs
__device__ float g_inv_out[3][NN];
__device__ float g_inv_in[3][NN];
__device__ int   g_deg_out[3][NN];
__device__ int   g_deg_in[3][NN];
__device__ int   g_offsets[3][NN + 1];
__device__ int   g_cursor[3][NN];
__device__ int   g_eidx[3][EE];
__device__ int   g_part[3][NB];

// ---------------------------------------------------------------------------
// Degrees (batched over 3 graphs)
// ---------------------------------------------------------------------------
__global__ void zero_deg_kernel() {
    int i = blockIdx.x * blockDim.x + threadIdx.x;
    if (i < 3 * NN) {
        ((int*)g_deg_out)[i] = 0;
        ((int*)g_deg_in)[i]  = 0;
    }
}

__global__ void count_deg_kernel(Ptrs3 p) {
    const int g = blockIdx.y;
    int e = blockIdx.x * blockDim.x + threadIdx.x;
    if (e < EE) {
        atomicAdd(&g_deg_out[g][p.src[g][e]], 1);
        atomicAdd(&g_deg_in[g][p.dst[g][e]], 1);
    }
}

__global__ void inv_sqrt_kernel() {
    int i = blockIdx.x * blockDim.x + threadIdx.x;
    if (i < 3 * NN) {
        ((float*)g_inv_out)[i] = rsqrtf(fmaxf((float)((int*)g_deg_out)[i], 1.0f));
        ((float*)g_inv_in)[i]  = rsqrtf(fmaxf((float)((int*)g_deg_in)[i],  1.0f));
    }
}

// ---------------------------------------------------------------------------
// Multi-block exclusive scan of deg_in -> offsets (+cursor), batched 3 graphs
// ---------------------------------------------------------------------------
__global__ void __launch_bounds__(256)
scan_k1() {                                   // block partial sums
    __shared__ int sm[256];
    const int g = blockIdx.y;
    const int i = blockIdx.x * 256 + threadIdx.x;
    int v = (i < NN) ? g_deg_in[g][i] : 0;
    sm[threadIdx.x] = v;
    __syncthreads();
    for (int off = 128; off > 0; off >>= 1) {
        if (threadIdx.x < off) sm[threadIdx.x] += sm[threadIdx.x + off];
        __syncthreads();
    }
    if (threadIdx.x == 0) g_part[g][blockIdx.x] = sm[0];
}

__global__ void __launch_bounds__(256)
scan_k2() {                                   // exclusive scan of partials
    __shared__ int sm[256];
    const int g = blockIdx.x;
    const int t = threadIdx.x;
    int v = (t < NB) ? g_part[g][t] : 0;
    sm[t] = v;
    __syncthreads();
    for (int off = 1; off < 256; off <<= 1) {
        int tv = (t >= off) ? sm[t - off] : 0;
        __syncthreads();
        sm[t] += tv;
        __syncthreads();
    }
    if (t < NB) g_part[g][t] = sm[t] - v;     // exclusive base
    if (t == 0) g_offsets[g][NN] = EE;
}

__global__ void __launch_bounds__(256)
scan_k3() {                                   // per-block exclusive scan + base
    __shared__ int sm[256];
    const int g = blockIdx.y;
    const int i = blockIdx.x * 256 + threadIdx.x;
    const int t = threadIdx.x;
    int v = (i < NN) ? g_deg_in[g][i] : 0;
    sm[t] = v;
    __syncthreads();
    for (int off = 1; off < 256; off <<= 1) {
        int tv = (t >= off) ? sm[t - off] : 0;
        __syncthreads();
        sm[t] += tv;
        __syncthreads();
    }
    if (i < NN) {
        int excl = sm[t] - v + g_part[g][blockIdx.x];
        g_offsets[g][i] = excl;
        g_cursor[g][i]  = excl;
    }
}

// ---------------------------------------------------------------------------
// Fill CSR: group src ids by dst (batched)
// ---------------------------------------------------------------------------
__global__ void fill_csr_kernel(Ptrs3 p) {
    const int g = blockIdx.y;
    int e = blockIdx.x * blockDim.x + threadIdx.x;
    if (e < EE) {
        int pos = atomicAdd(&g_cursor[g][p.dst[g][e]], 1);
        g_eidx[g][pos] = p.src[g][e];
    }
}

// ---------------------------------------------------------------------------
// SGEMM: C[g][M,128] = (A[g][M,K] @ B[K,128]) * inv_out[g][row]
// BM=128, BN=128, BK=8, 256 threads, 8x8/thread, double-buffered.
// ---------------------------------------------------------------------------
template <bool LAYER1>
__global__ void __launch_bounds__(256)
sgemm_scaled_kernel(Ptrs3 p, const float* __restrict__ B, int K)
{
    __shared__ float As[2][8][128];
    __shared__ float Bs[2][8][128];

    const int g = blockIdx.y;
    const float* __restrict__ A = LAYER1 ? p.feat[g] : g_a[g];
    float* __restrict__ C = g_h[g];
    const float* __restrict__ rowscale = g_inv_out[g];
    const int M = NN;

    const int tid = threadIdx.x;
    const int block_row = blockIdx.x * 128;

    const int arow = tid >> 1;
    const int ak4  = (tid & 1) * 4;
    const int bk    = tid >> 5;
    const int bcol4 = (tid & 31) * 4;

    const int ty = tid >> 4;
    const int tx = tid & 15;
    const int row0 = ty * 8;
    const int col0 = tx * 8;

    float acc[8][8];
    #pragma unroll
    for (int i = 0; i < 8; i++)
        #pragma unroll
        for (int j = 0; j < 8; j++) acc[i][j] = 0.0f;

    const int gr = block_row + arow;
    const bool a_ok = (gr < M);

    float4 av = make_float4(0.f, 0.f, 0.f, 0.f);
    if (a_ok) av = *(const float4*)&A[(size_t)gr * K + ak4];
    float4 bv = *(const float4*)&B[(size_t)bk * 128 + bcol4];

    As[0][ak4 + 0][arow] = av.x;
    As[0][ak4 + 1][arow] = av.y;
    As[0][ak4 + 2][arow] = av.z;
    As[0][ak4 + 3][arow] = av.w;
    *(float4*)&Bs[0][bk][bcol4] = bv;
    __syncthreads();

    int cur = 0;
    for (int k0 = 0; k0 < K; k0 += 8) {
        const bool has_next = (k0 + 8 < K);
        if (has_next) {
            av = make_float4(0.f, 0.f, 0.f, 0.f);
            if (a_ok) av = *(const float4*)&A[(size_t)gr * K + k0 + 8 + ak4];
            bv = *(const float4*)&B[(size_t)(k0 + 8 + bk) * 128 + bcol4];
        }

        #pragma unroll
        for (int kk = 0; kk < 8; kk++) {
            float ra[8], rb[8];
            *(float4*)&ra[0] = *(float4*)&As[cur][kk][row0];
            *(float4*)&ra[4] = *(float4*)&As[cur][kk][row0 + 4];
            *(float4*)&rb[0] = *(float4*)&Bs[cur][kk][col0];
            *(float4*)&rb[4] = *(float4*)&Bs[cur][kk][col0 + 4];
            #pragma unroll
            for (int i = 0; i < 8; i++)
                #pragma unroll
                for (int j = 0; j < 8; j++)
                    acc[i][j] = fmaf(ra[i], rb[j], acc[i][j]);
        }

        if (has_next) {
            const int nxt = cur ^ 1;
            As[nxt][ak4 + 0][arow] = av.x;
            As[nxt][ak4 + 1][arow] = av.y;
            As[nxt][ak4 + 2][arow] = av.z;
            As[nxt][ak4 + 3][arow] = av.w;
            *(float4*)&Bs[nxt][bk][bcol4] = bv;
            __syncthreads();
            cur = nxt;
        }
    }

    #pragma unroll
    for (int i = 0; i < 8; i++) {
        const int grr = block_row + row0 + i;
        if (grr < M) {
            const float s = rowscale[grr];
            float4 v0, v1;
            v0.x = acc[i][0] * s; v0.y = acc[i][1] * s;
            v0.z = acc[i][2] * s; v0.w = acc[i][3] * s;
            v1.x = acc[i][4] * s; v1.y = acc[i][5] * s;
            v1.z = acc[i][6] * s; v1.w = acc[i][7] * s;
            *(float4*)&C[(size_t)grr * 128 + col0]     = v0;
            *(float4*)&C[(size_t)grr * 128 + col0 + 4] = v1;
        }
    }
}

// ---------------------------------------------------------------------------
// CSR aggregation + fused epilogue (batched):
//   dstbuf[d,:] = act( (sum_{e: dst=d} h[src_e,:]) * inv_in[d] + bias[:] )
// One warp per dst node.
// ---------------------------------------------------------------------------
template <bool DO_RELU, bool TO_OUT>
__global__ void __launch_bounds__(256)
aggregate_kernel(const float* __restrict__ bias, float* __restrict__ out)
{
    const int g    = blockIdx.y;
    const int gid  = blockIdx.x * blockDim.x + threadIdx.x;
    const int d    = gid >> 5;
    const int lane = threadIdx.x & 31;
    if (d >= NN) return;

    const float* __restrict__ h = g_h[g];
    const int beg = g_offsets[g][d];
    const int end = g_offsets[g][d + 1];

    float4 acc = make_float4(0.f, 0.f, 0.f, 0.f);
    for (int j = beg; j < end; j++) {
        const int s = g_eidx[g][j];
        const float4 v = *(const float4*)&h[(size_t)s * 128 + lane * 4];
        acc.x += v.x; acc.y += v.y; acc.z += v.z; acc.w += v.w;
    }

    const float sc = g_inv_in[g][d];
    const float4 b = *(const float4*)&bias[lane * 4];
    float4 r;
    r.x = fmaf(acc.x, sc, b.x);
    r.y = fmaf(acc.y, sc, b.y);
    r.z = fmaf(acc.z, sc, b.z);
    r.w = fmaf(acc.w, sc, b.w);
    if (DO_RELU) {
        r.x = fmaxf(r.x, 0.f); r.y = fmaxf(r.y, 0.f);
        r.z = fmaxf(r.z, 0.f); r.w = fmaxf(r.w, 0.f);
    }
    float* dstp = TO_OUT ? (out + (size_t)g * NN * 128) : g_a[g];
    *(float4*)&dstp[(size_t)d * 128 + lane * 4] = r;
}

// ---------------------------------------------------------------------------
extern "C" void kernel_launch(void* const* d_in, const int* in_sizes, int n_in,
                              void* d_out, int out_size)
{
    Ptrs3 p;
    p.feat[0] = (const float*)d_in[0];
    p.src[0]  = (const int*)  d_in[1];
    p.dst[0]  = (const int*)  d_in[2];
    p.feat[1] = (const float*)d_in[3];
    p.src[1]  = (const int*)  d_in[4];
    p.dst[1]  = (const int*)  d_in[5];
    p.feat[2] = (const float*)d_in[6];
    p.src[2]  = (const int*)  d_in[7];
    p.dst[2]  = (const int*)  d_in[8];
    const float* W1 = (const float*)d_in[9];
    const float* b1 = (const float*)d_in[10];
    const float* W2 = (const float*)d_in[11];
    const float* b2 = (const float*)d_in[12];
    float* out = (float*)d_out;

    const int nT = 256;
    const dim3 gridE3((EE + nT - 1) / nT, 3);
    const dim3 gridScan(NB, 3);
    const dim3 gridGemm((NN + 127) / 128, 3);
    const dim3 gridAgg((NN * 32 + nT - 1) / nT, 3);
    const int  gridN3 = (3 * NN + nT - 1) / nT;

    // Graph structure for all 3 graphs
    zero_deg_kernel<<<gridN3, nT>>>();
    count_deg_kernel<<<gridE3, nT>>>(p);
    inv_sqrt_kernel<<<gridN3, nT>>>();
    scan_k1<<<gridScan, nT>>>();
    scan_k2<<<3, nT>>>();
    scan_k3<<<gridScan, nT>>>();
    fill_csr_kernel<<<gridE3, nT>>>(p);

    // Layer 1 (all graphs)
    sgemm_scaled_kernel<true><<<gridGemm, nT>>>(p, W1, INDIM);
    aggregate_kernel<true, false><<<gridAgg, nT>>>(b1, out);

    // Layer 2 (all graphs)
    sgemm_scaled_kernel<false><<<gridGemm, nT>>>(p, W2, HID);
    aggregate_kernel<false, true><<<gridAgg, nT>>>(b2, out);
}